// round 1
// baseline (speedup 1.0000x reference)
#include <cuda_runtime.h>
#include <math.h>

#define BB 4
#define NN 8192
#define KK 32
#define DD 64
#define BN (BB*NN)
#define PT 4
#define NWARP 8
#define NTASK (BN/PT)

// scratch (device globals; no allocation)
__device__ float g_F1a[BN*DD];
__device__ float g_F1b[BN*DD];
__device__ float g_F1c[BN*DD];
__device__ float g_z[BN*DD];
__device__ float g_rh[BN*DD];

__device__ __forceinline__ float lrelu(float v){ return v > 0.f ? v : 0.1f*v; }
__device__ __forceinline__ float sigm(float v){ return 1.f/(1.f+expf(-v)); }

// F1 = [s0|s1] @ W (128x64), for NB branches at once. Warp handles PT points.
template<int NB>
__global__ void linear_kernel(const float* __restrict__ s0, const float* __restrict__ s1,
                              const float* __restrict__ Wa, const float* __restrict__ Wb,
                              float* __restrict__ oA, float* __restrict__ oB)
{
    extern __shared__ float sm[];
    float* sW = sm;                 // NB * 8192
    float* sF = sm + NB*8192;       // NWARP * PT * 128
    int tid = threadIdx.x, w = tid>>5, L = tid&31;
    for (int i = tid; i < 8192; i += blockDim.x) sW[i] = Wa[i];
    if (NB == 2) for (int i = tid; i < 8192; i += blockDim.x) sW[8192+i] = Wb[i];
    __syncthreads();
    float* f = sF + w*(PT*128);
    for (int t = blockIdx.x*NWARP + w; t < NTASK; t += gridDim.x*NWARP) {
        int p0 = t*PT;
        #pragma unroll
        for (int q = 0; q < PT; q++) {
            int p = p0 + q;
            f[q*128 + L]      = s0[p*64 + L];
            f[q*128 + 32 + L] = s0[p*64 + 32 + L];
            f[q*128 + 64 + L] = s1[p*64 + L];
            f[q*128 + 96 + L] = s1[p*64 + 32 + L];
        }
        __syncwarp();
        float acc[NB][PT][2];
        #pragma unroll
        for (int i2 = 0; i2 < NB; i2++)
            #pragma unroll
            for (int q = 0; q < PT; q++) { acc[i2][q][0] = 0.f; acc[i2][q][1] = 0.f; }
        #pragma unroll 16
        for (int c = 0; c < 128; c++) {
            float2 wa = *(const float2*)&sW[c*64 + 2*L];
            float2 wb = make_float2(0.f, 0.f);
            if (NB == 2) wb = *(const float2*)&sW[8192 + c*64 + 2*L];
            #pragma unroll
            for (int q = 0; q < PT; q++) {
                float fc = f[q*128 + c];
                acc[0][q][0] += fc*wa.x; acc[0][q][1] += fc*wa.y;
                if (NB == 2) { acc[1][q][0] += fc*wb.x; acc[1][q][1] += fc*wb.y; }
            }
        }
        #pragma unroll
        for (int q = 0; q < PT; q++) {
            *(float2*)&oA[(p0+q)*64 + 2*L] = make_float2(acc[0][q][0], acc[0][q][1]);
            if (NB == 2)
                *(float2*)&oB[(p0+q)*64 + 2*L] = make_float2(acc[1][q][0], acc[1][q][1]);
        }
        __syncwarp();
    }
}

// Branches 0+1: gather F1 rows, add edge term, max-pool, lrelu, 2-layer MLP.
// z = sigmoid(o0) stored; rh = sigmoid(o1)*h stored.
__global__ void gate01_kernel(const float* __restrict__ h,
    const float* __restrict__ W1, const float* __restrict__ b1,
    const float* __restrict__ W2, const float* __restrict__ b2,
    const float* __restrict__ W3, const float* __restrict__ b3,
    const int* __restrict__ nidx, const float* __restrict__ ef,
    float* __restrict__ z_out, float* __restrict__ rh_out)
{
    extern __shared__ float sm[];
    float* sW2a = sm;
    float* sW2b = sm + 4096;
    float* sW3a = sm + 8192;
    float* sW3b = sm + 12288;
    float* sStg = sm + 16384;       // NWARP * 512
    int tid = threadIdx.x, w = tid>>5, L = tid&31;
    for (int i = tid; i < 4096; i += blockDim.x) {
        sW2a[i] = W2[i];        sW2b[i] = W2[4096 + i];
        sW3a[i] = W3[i];        sW3b[i] = W3[4096 + i];
    }
    __syncthreads();

    const float* eWa = W1 + 128*64;                // branch 0 edge rows
    const float* eWb = W1 + 131*64 + 128*64;       // branch 1 edge rows
    float wEaL[3], wEaH[3], wEbL[3], wEbH[3];
    #pragma unroll
    for (int j = 0; j < 3; j++) {
        wEaL[j] = eWa[j*64 + L];  wEaH[j] = eWa[j*64 + L + 32];
        wEbL[j] = eWb[j*64 + L];  wEbH[j] = eWb[j*64 + L + 32];
    }
    float b1aL = b1[L], b1aH = b1[L+32], b1bL = b1[64+L], b1bH = b1[64+L+32];
    float2 b2a = *(const float2*)&b2[2*L],      b2b = *(const float2*)&b2[64 + 2*L];
    float2 b3a = *(const float2*)&b3[2*L],      b3b = *(const float2*)&b3[64 + 2*L];

    float* st = sStg + w*512;   // [0:256) pooled/y2 branch a, [256:512) branch b
    for (int t = blockIdx.x*NWARP + w; t < NTASK; t += gridDim.x*NWARP) {
        int p0 = t*PT;
        int bb = p0 >> 13;   // / NN
        const float* Fa = g_F1a + (size_t)bb*NN*64;
        const float* Fb = g_F1b + (size_t)bb*NN*64;
        #pragma unroll
        for (int q = 0; q < PT; q++) {
            int p = p0 + q;
            int ii = nidx[p*KK + L];
            const float* ep = ef + (size_t)p*96;
            float aL = -1e30f, aH = -1e30f, cL = -1e30f, cH = -1e30f;
            #pragma unroll 8
            for (int k = 0; k < KK; k++) {
                int fi = __shfl_sync(0xffffffffu, ii, k);
                const float* ra = Fa + fi*64;
                const float* rb = Fb + fi*64;
                float vaL = __ldg(ra + L),     vaH = __ldg(ra + L + 32);
                float vbL = __ldg(rb + L),     vbH = __ldg(rb + L + 32);
                float e0 = __ldg(ep + 3*k), e1 = __ldg(ep + 3*k + 1), e2 = __ldg(ep + 3*k + 2);
                aL = fmaxf(aL, vaL + e0*wEaL[0] + e1*wEaL[1] + e2*wEaL[2]);
                aH = fmaxf(aH, vaH + e0*wEaH[0] + e1*wEaH[1] + e2*wEaH[2]);
                cL = fmaxf(cL, vbL + e0*wEbL[0] + e1*wEbL[1] + e2*wEbL[2]);
                cH = fmaxf(cH, vbH + e0*wEbH[0] + e1*wEbH[1] + e2*wEbH[2]);
            }
            st[q*64 + L]          = lrelu(aL + b1aL);
            st[q*64 + L + 32]     = lrelu(aH + b1aH);
            st[256 + q*64 + L]      = lrelu(cL + b1bL);
            st[256 + q*64 + L + 32] = lrelu(cH + b1bH);
        }
        __syncwarp();
        // layer 1: y = lrelu(pooled @ W2 + b2)
        float ya[PT][2], yb[PT][2];
        #pragma unroll
        for (int q = 0; q < PT; q++) {
            ya[q][0] = b2a.x; ya[q][1] = b2a.y;
            yb[q][0] = b2b.x; yb[q][1] = b2b.y;
        }
        #pragma unroll 8
        for (int j = 0; j < 64; j++) {
            float2 w2a = *(const float2*)&sW2a[j*64 + 2*L];
            float2 w2b = *(const float2*)&sW2b[j*64 + 2*L];
            #pragma unroll
            for (int q = 0; q < PT; q++) {
                float pa = st[q*64 + j];
                float pb = st[256 + q*64 + j];
                ya[q][0] += pa*w2a.x; ya[q][1] += pa*w2a.y;
                yb[q][0] += pb*w2b.x; yb[q][1] += pb*w2b.y;
            }
        }
        __syncwarp();
        #pragma unroll
        for (int q = 0; q < PT; q++) {
            st[q*64 + 2*L]         = lrelu(ya[q][0]);
            st[q*64 + 2*L + 1]     = lrelu(ya[q][1]);
            st[256 + q*64 + 2*L]     = lrelu(yb[q][0]);
            st[256 + q*64 + 2*L + 1] = lrelu(yb[q][1]);
        }
        __syncwarp();
        // layer 2: o = y @ W3 + b3
        float oa[PT][2], ob[PT][2];
        #pragma unroll
        for (int q = 0; q < PT; q++) {
            oa[q][0] = b3a.x; oa[q][1] = b3a.y;
            ob[q][0] = b3b.x; ob[q][1] = b3b.y;
        }
        #pragma unroll 8
        for (int j = 0; j < 64; j++) {
            float2 w3a = *(const float2*)&sW3a[j*64 + 2*L];
            float2 w3b = *(const float2*)&sW3b[j*64 + 2*L];
            #pragma unroll
            for (int q = 0; q < PT; q++) {
                float y_a = st[q*64 + j];
                float y_b = st[256 + q*64 + j];
                oa[q][0] += y_a*w3a.x; oa[q][1] += y_a*w3a.y;
                ob[q][0] += y_b*w3b.x; ob[q][1] += y_b*w3b.y;
            }
        }
        #pragma unroll
        for (int q = 0; q < PT; q++) {
            int p = p0 + q;
            float z0 = sigm(oa[q][0]), z1 = sigm(oa[q][1]);
            *(float2*)&z_out[p*64 + 2*L] = make_float2(z0, z1);
            float r0 = sigm(ob[q][0]), r1 = sigm(ob[q][1]);
            float2 hv = *(const float2*)&h[p*64 + 2*L];
            *(float2*)&rh_out[p*64 + 2*L] = make_float2(r0*hv.x, r1*hv.y);
        }
        __syncwarp();
    }
}

// Branch 2: gather F1c, pool, MLP, q = tanh(o); out = h + z*(q - h).
__global__ void gate2_kernel(const float* __restrict__ h,
    const float* __restrict__ W1, const float* __restrict__ b1,
    const float* __restrict__ W2, const float* __restrict__ b2,
    const float* __restrict__ W3, const float* __restrict__ b3,
    const int* __restrict__ nidx, const float* __restrict__ ef,
    float* __restrict__ out)
{
    extern __shared__ float sm[];
    float* sW2 = sm;
    float* sW3 = sm + 4096;
    float* sStg = sm + 8192;        // NWARP * 256
    int tid = threadIdx.x, w = tid>>5, L = tid&31;
    for (int i = tid; i < 4096; i += blockDim.x) {
        sW2[i] = W2[2*4096 + i];
        sW3[i] = W3[2*4096 + i];
    }
    __syncthreads();

    const float* eWc = W1 + 2*131*64 + 128*64;
    float wEL[3], wEH[3];
    #pragma unroll
    for (int j = 0; j < 3; j++) { wEL[j] = eWc[j*64 + L]; wEH[j] = eWc[j*64 + L + 32]; }
    float b1L = b1[128 + L], b1H = b1[128 + L + 32];
    float2 b2c = *(const float2*)&b2[128 + 2*L];
    float2 b3c = *(const float2*)&b3[128 + 2*L];

    float* st = sStg + w*256;
    for (int t = blockIdx.x*NWARP + w; t < NTASK; t += gridDim.x*NWARP) {
        int p0 = t*PT;
        int bb = p0 >> 13;
        const float* Fc = g_F1c + (size_t)bb*NN*64;
        #pragma unroll
        for (int q = 0; q < PT; q++) {
            int p = p0 + q;
            int ii = nidx[p*KK + L];
            const float* ep = ef + (size_t)p*96;
            float aL = -1e30f, aH = -1e30f;
            #pragma unroll 8
            for (int k = 0; k < KK; k++) {
                int fi = __shfl_sync(0xffffffffu, ii, k);
                const float* rc = Fc + fi*64;
                float vL = __ldg(rc + L), vH = __ldg(rc + L + 32);
                float e0 = __ldg(ep + 3*k), e1 = __ldg(ep + 3*k + 1), e2 = __ldg(ep + 3*k + 2);
                aL = fmaxf(aL, vL + e0*wEL[0] + e1*wEL[1] + e2*wEL[2]);
                aH = fmaxf(aH, vH + e0*wEH[0] + e1*wEH[1] + e2*wEH[2]);
            }
            st[q*64 + L]      = lrelu(aL + b1L);
            st[q*64 + L + 32] = lrelu(aH + b1H);
        }
        __syncwarp();
        float yc[PT][2];
        #pragma unroll
        for (int q = 0; q < PT; q++) { yc[q][0] = b2c.x; yc[q][1] = b2c.y; }
        #pragma unroll 8
        for (int j = 0; j < 64; j++) {
            float2 w2 = *(const float2*)&sW2[j*64 + 2*L];
            #pragma unroll
            for (int q = 0; q < PT; q++) {
                float pv = st[q*64 + j];
                yc[q][0] += pv*w2.x; yc[q][1] += pv*w2.y;
            }
        }
        __syncwarp();
        #pragma unroll
        for (int q = 0; q < PT; q++) {
            st[q*64 + 2*L]     = lrelu(yc[q][0]);
            st[q*64 + 2*L + 1] = lrelu(yc[q][1]);
        }
        __syncwarp();
        float oc[PT][2];
        #pragma unroll
        for (int q = 0; q < PT; q++) { oc[q][0] = b3c.x; oc[q][1] = b3c.y; }
        #pragma unroll 8
        for (int j = 0; j < 64; j++) {
            float2 w3 = *(const float2*)&sW3[j*64 + 2*L];
            #pragma unroll
            for (int q = 0; q < PT; q++) {
                float yv = st[q*64 + j];
                oc[q][0] += yv*w3.x; oc[q][1] += yv*w3.y;
            }
        }
        #pragma unroll
        for (int q = 0; q < PT; q++) {
            int p = p0 + q;
            float q0 = tanhf(oc[q][0]), q1 = tanhf(oc[q][1]);
            float2 zv = *(const float2*)&g_z[p*64 + 2*L];
            float2 hv = *(const float2*)&h[p*64 + 2*L];
            float o0 = hv.x + zv.x*(q0 - hv.x);
            float o1 = hv.y + zv.y*(q1 - hv.y);
            *(float2*)&out[p*64 + 2*L] = make_float2(o0, o1);
        }
        __syncwarp();
    }
}

extern "C" void kernel_launch(void* const* d_in, const int* in_sizes, int n_in,
                              void* d_out, int out_size)
{
    const float* h   = (const float*)d_in[0];
    const float* x   = (const float*)d_in[1];
    // d_in[2] = c, unused (matches reference)
    const float* W1  = (const float*)d_in[3];
    const float* b1  = (const float*)d_in[4];
    const float* W2  = (const float*)d_in[5];
    const float* b2  = (const float*)d_in[6];
    const float* W3  = (const float*)d_in[7];
    const float* b3  = (const float*)d_in[8];
    const int*   nidx = (const int*)d_in[9];
    const float* ef  = (const float*)d_in[10];
    float* out = (float*)d_out;

    void *pF1a, *pF1b, *pF1c, *pz, *prh;
    cudaGetSymbolAddress(&pF1a, g_F1a);
    cudaGetSymbolAddress(&pF1b, g_F1b);
    cudaGetSymbolAddress(&pF1c, g_F1c);
    cudaGetSymbolAddress(&pz,   g_z);
    cudaGetSymbolAddress(&prh,  g_rh);

    const int smem_lin2 = (2*8192 + NWARP*PT*128) * 4;   // 81920
    const int smem_lin1 = (1*8192 + NWARP*PT*128) * 4;   // 49152
    const int smem_g01  = (16384 + NWARP*512) * 4;        // 81920
    const int smem_g2   = (8192 + NWARP*256) * 4;         // 40960

    cudaFuncSetAttribute(linear_kernel<2>, cudaFuncAttributeMaxDynamicSharedMemorySize, smem_lin2);
    cudaFuncSetAttribute(linear_kernel<1>, cudaFuncAttributeMaxDynamicSharedMemorySize, smem_lin1);
    cudaFuncSetAttribute(gate01_kernel,    cudaFuncAttributeMaxDynamicSharedMemorySize, smem_g01);
    cudaFuncSetAttribute(gate2_kernel,     cudaFuncAttributeMaxDynamicSharedMemorySize, smem_g2);

    const int grid = 592;
    dim3 blk(256);

    // F1_0, F1_1 = [h|x] @ W1a[0..1]
    linear_kernel<2><<<grid, blk, smem_lin2>>>(h, x, W1, W1 + 131*64,
                                               (float*)pF1a, (float*)pF1b);
    // z, r*h
    gate01_kernel<<<grid, blk, smem_g01>>>(h, W1, b1, W2, b2, W3, b3, nidx, ef,
                                           (float*)pz, (float*)prh);
    // F1_2 = [r*h|x] @ W1a[2]
    linear_kernel<1><<<grid, blk, smem_lin1>>>((const float*)prh, x, W1 + 2*131*64, nullptr,
                                               (float*)pF1c, nullptr);
    // q and final output
    gate2_kernel<<<grid, blk, smem_g2>>>(h, W1, b1, W2, b2, W3, b3, nidx, ef, out);
}

// round 2
// speedup vs baseline: 1.2428x; 1.2428x over previous
#include <cuda_runtime.h>
#include <cuda_fp16.h>
#include <math.h>

#define BB 4
#define NN 8192
#define KK 32
#define BN (BB*NN)
#define PT 4
#define NWARP 8
#define NTASK (BN/PT)

// scratch (device globals; no allocation)
// g_F1ab row (per point): 32 uint2 groups; group L = {a[2L],a[2L+1],b[2L],b[2L+1]} fp16
__device__ uint2   g_F1ab[BN*32];
__device__ __half2 g_F1c[BN*32];
__device__ float   g_z[BN*64];
__device__ float   g_rh[BN*64];

__device__ __forceinline__ float lrelu(float v){ return v > 0.f ? v : 0.1f*v; }
__device__ __forceinline__ float sigm(float v){ return 1.f/(1.f+expf(-v)); }

// shfl-broadcast element j of the 96 edge floats held in er0/er1/er2 (j compile-time)
#define EGET(j) __shfl_sync(0xffffffffu, ((j) < 32 ? er0 : ((j) < 64 ? er1 : er2)), (j) & 31)

// ---------------- linear2: F1ab = [h|x] @ {W1a[0], W1a[1]}, packed fp16 out ----------------
__global__ void linear2_kernel(const float* __restrict__ s0, const float* __restrict__ s1,
                               const float* __restrict__ Wa, const float* __restrict__ Wb,
                               uint2* __restrict__ oAB)
{
    extern __shared__ float sm[];
    float* sW4 = sm;                 // 128*128 floats, packed {a0,a1,b0,b1} per (c,L)
    float* sF  = sm + 16384;         // NWARP * PT * 128
    int tid = threadIdx.x, w = tid>>5, L = tid&31;
    for (int i = tid; i < 4096; i += blockDim.x) {
        int c = i >> 5, l = i & 31;
        float4 wv;
        wv.x = Wa[c*64 + 2*l];   wv.y = Wa[c*64 + 2*l + 1];
        wv.z = Wb[c*64 + 2*l];   wv.w = Wb[c*64 + 2*l + 1];
        ((float4*)sW4)[i] = wv;
    }
    __syncthreads();
    float* f = sF + w*(PT*128);
    for (int t = blockIdx.x*NWARP + w; t < NTASK; t += gridDim.x*NWARP) {
        int p0 = t*PT;
        #pragma unroll
        for (int q = 0; q < PT; q++) {
            int p = p0 + q;
            f[q*128 + L]      = s0[p*64 + L];
            f[q*128 + 32 + L] = s0[p*64 + 32 + L];
            f[q*128 + 64 + L] = s1[p*64 + L];
            f[q*128 + 96 + L] = s1[p*64 + 32 + L];
        }
        __syncwarp();
        float acc[PT][4];
        #pragma unroll
        for (int q = 0; q < PT; q++)
            #pragma unroll
            for (int d = 0; d < 4; d++) acc[q][d] = 0.f;
        #pragma unroll 16
        for (int c = 0; c < 128; c++) {
            float4 wv = ((const float4*)sW4)[c*32 + L];
            #pragma unroll
            for (int q = 0; q < PT; q++) {
                float fc = f[q*128 + c];
                acc[q][0] += fc*wv.x; acc[q][1] += fc*wv.y;
                acc[q][2] += fc*wv.z; acc[q][3] += fc*wv.w;
            }
        }
        #pragma unroll
        for (int q = 0; q < PT; q++) {
            __half2 ha = __floats2half2_rn(acc[q][0], acc[q][1]);
            __half2 hb = __floats2half2_rn(acc[q][2], acc[q][3]);
            uint2 o;
            o.x = *(const unsigned int*)&ha;
            o.y = *(const unsigned int*)&hb;
            oAB[(size_t)(p0+q)*32 + L] = o;
        }
        __syncwarp();
    }
}

// ---------------- linear1: F1c = [rh|x] @ W1a[2], fp16 out ----------------
__global__ void linear1_kernel(const float* __restrict__ s0, const float* __restrict__ s1,
                               const float* __restrict__ Wc, __half2* __restrict__ oC)
{
    extern __shared__ float sm[];
    float* sW = sm;                 // 8192
    float* sF = sm + 8192;          // NWARP * PT * 128
    int tid = threadIdx.x, w = tid>>5, L = tid&31;
    for (int i = tid; i < 8192; i += blockDim.x) sW[i] = Wc[i];
    __syncthreads();
    float* f = sF + w*(PT*128);
    for (int t = blockIdx.x*NWARP + w; t < NTASK; t += gridDim.x*NWARP) {
        int p0 = t*PT;
        #pragma unroll
        for (int q = 0; q < PT; q++) {
            int p = p0 + q;
            f[q*128 + L]      = s0[p*64 + L];
            f[q*128 + 32 + L] = s0[p*64 + 32 + L];
            f[q*128 + 64 + L] = s1[p*64 + L];
            f[q*128 + 96 + L] = s1[p*64 + 32 + L];
        }
        __syncwarp();
        float acc[PT][2];
        #pragma unroll
        for (int q = 0; q < PT; q++) { acc[q][0] = 0.f; acc[q][1] = 0.f; }
        #pragma unroll 16
        for (int c = 0; c < 128; c++) {
            float2 wv = *(const float2*)&sW[c*64 + 2*L];
            #pragma unroll
            for (int q = 0; q < PT; q++) {
                float fc = f[q*128 + c];
                acc[q][0] += fc*wv.x; acc[q][1] += fc*wv.y;
            }
        }
        #pragma unroll
        for (int q = 0; q < PT; q++)
            oC[(size_t)(p0+q)*32 + L] = __floats2half2_rn(acc[q][0], acc[q][1]);
        __syncwarp();
    }
}

// ---------------- gate01: branches 0+1 -> z, r*h ----------------
__global__ void gate01_kernel(const float* __restrict__ h,
    const float* __restrict__ W1, const float* __restrict__ b1,
    const float* __restrict__ W2, const float* __restrict__ b2,
    const float* __restrict__ W3, const float* __restrict__ b3,
    const int* __restrict__ nidx, const float* __restrict__ ef,
    float* __restrict__ z_out, float* __restrict__ rh_out)
{
    extern __shared__ float sm[];
    float* sW2 = sm;                // 64*128 packed {a0,a1,b0,b1}
    float* sW3 = sm + 8192;         // 64*128 packed
    float* sStg = sm + 16384;       // NWARP * 512
    int tid = threadIdx.x, w = tid>>5, L = tid&31;
    for (int i = tid; i < 2048; i += blockDim.x) {
        int j = i >> 5, l = i & 31;
        float4 w2, w3;
        w2.x = W2[j*64 + 2*l];        w2.y = W2[j*64 + 2*l + 1];
        w2.z = W2[4096 + j*64 + 2*l]; w2.w = W2[4096 + j*64 + 2*l + 1];
        ((float4*)sW2)[i] = w2;
        w3.x = W3[j*64 + 2*l];        w3.y = W3[j*64 + 2*l + 1];
        w3.z = W3[4096 + j*64 + 2*l]; w3.w = W3[4096 + j*64 + 2*l + 1];
        ((float4*)sW3)[i] = w3;
    }
    __syncthreads();

    const float* eWa = W1 + 128*64;                // branch 0 edge rows
    const float* eWb = W1 + 131*64 + 128*64;       // branch 1 edge rows
    float2 wEa[3], wEb[3];
    #pragma unroll
    for (int j = 0; j < 3; j++) {
        wEa[j] = *(const float2*)&eWa[j*64 + 2*L];
        wEb[j] = *(const float2*)&eWb[j*64 + 2*L];
    }
    float2 b1a = *(const float2*)&b1[2*L],      b1b = *(const float2*)&b1[64 + 2*L];
    float2 b2a = *(const float2*)&b2[2*L],      b2b = *(const float2*)&b2[64 + 2*L];
    float2 b3a = *(const float2*)&b3[2*L],      b3b = *(const float2*)&b3[64 + 2*L];

    float* st = sStg + w*512;   // [0:256) branch a, [256:512) branch b
    for (int t = blockIdx.x*NWARP + w; t < NTASK; t += gridDim.x*NWARP) {
        int p0 = t*PT;
        int bb = p0 >> 13;
        const uint2* Fab = g_F1ab + (size_t)bb*NN*32;
        #pragma unroll
        for (int q = 0; q < PT; q++) {
            int p = p0 + q;
            int ii = nidx[p*KK + L];
            float er0 = ef[(size_t)p*96 + L];
            float er1 = ef[(size_t)p*96 + 32 + L];
            float er2 = ef[(size_t)p*96 + 64 + L];
            __half2 ma = __float2half2_rn(-6.0e4f);
            __half2 mb = ma;
            #pragma unroll
            for (int k = 0; k < KK; k++) {
                int fi = __shfl_sync(0xffffffffu, ii, k);
                uint2 v = __ldg(&Fab[(size_t)fi*32 + L]);
                float e0 = EGET(3*k), e1 = EGET(3*k+1), e2 = EGET(3*k+2);
                float ea0 = fmaf(e2, wEa[2].x, fmaf(e1, wEa[1].x, e0*wEa[0].x));
                float ea1 = fmaf(e2, wEa[2].y, fmaf(e1, wEa[1].y, e0*wEa[0].y));
                float eb0 = fmaf(e2, wEb[2].x, fmaf(e1, wEb[1].x, e0*wEb[0].x));
                float eb1 = fmaf(e2, wEb[2].y, fmaf(e1, wEb[1].y, e0*wEb[0].y));
                __half2 ea = __floats2half2_rn(ea0, ea1);
                __half2 eb = __floats2half2_rn(eb0, eb1);
                ma = __hmax2(ma, __hadd2(*(const __half2*)&v.x, ea));
                mb = __hmax2(mb, __hadd2(*(const __half2*)&v.y, eb));
            }
            float2 fa = __half22float2(ma);
            float2 fb = __half22float2(mb);
            fa.x = lrelu(fa.x + b1a.x);  fa.y = lrelu(fa.y + b1a.y);
            fb.x = lrelu(fb.x + b1b.x);  fb.y = lrelu(fb.y + b1b.y);
            *(float2*)&st[q*64 + 2*L]       = fa;
            *(float2*)&st[256 + q*64 + 2*L] = fb;
        }
        __syncwarp();
        // layer 1
        float ya[PT][2], yb[PT][2];
        #pragma unroll
        for (int q = 0; q < PT; q++) {
            ya[q][0] = b2a.x; ya[q][1] = b2a.y;
            yb[q][0] = b2b.x; yb[q][1] = b2b.y;
        }
        #pragma unroll 8
        for (int j = 0; j < 64; j++) {
            float4 wv = ((const float4*)sW2)[j*32 + L];
            #pragma unroll
            for (int q = 0; q < PT; q++) {
                float pa = st[q*64 + j];
                float pb = st[256 + q*64 + j];
                ya[q][0] += pa*wv.x; ya[q][1] += pa*wv.y;
                yb[q][0] += pb*wv.z; yb[q][1] += pb*wv.w;
            }
        }
        __syncwarp();
        #pragma unroll
        for (int q = 0; q < PT; q++) {
            *(float2*)&st[q*64 + 2*L]       = make_float2(lrelu(ya[q][0]), lrelu(ya[q][1]));
            *(float2*)&st[256 + q*64 + 2*L] = make_float2(lrelu(yb[q][0]), lrelu(yb[q][1]));
        }
        __syncwarp();
        // layer 2
        float oa[PT][2], ob[PT][2];
        #pragma unroll
        for (int q = 0; q < PT; q++) {
            oa[q][0] = b3a.x; oa[q][1] = b3a.y;
            ob[q][0] = b3b.x; ob[q][1] = b3b.y;
        }
        #pragma unroll 8
        for (int j = 0; j < 64; j++) {
            float4 wv = ((const float4*)sW3)[j*32 + L];
            #pragma unroll
            for (int q = 0; q < PT; q++) {
                float y_a = st[q*64 + j];
                float y_b = st[256 + q*64 + j];
                oa[q][0] += y_a*wv.x; oa[q][1] += y_a*wv.y;
                ob[q][0] += y_b*wv.z; ob[q][1] += y_b*wv.w;
            }
        }
        #pragma unroll
        for (int q = 0; q < PT; q++) {
            int p = p0 + q;
            float z0 = sigm(oa[q][0]), z1 = sigm(oa[q][1]);
            *(float2*)&z_out[(size_t)p*64 + 2*L] = make_float2(z0, z1);
            float r0 = sigm(ob[q][0]), r1 = sigm(ob[q][1]);
            float2 hv = *(const float2*)&h[(size_t)p*64 + 2*L];
            *(float2*)&rh_out[(size_t)p*64 + 2*L] = make_float2(r0*hv.x, r1*hv.y);
        }
        __syncwarp();
    }
}

// ---------------- gate2: branch 2 -> q; out = h + z*(q-h) ----------------
__global__ void gate2_kernel(const float* __restrict__ h,
    const float* __restrict__ W1, const float* __restrict__ b1,
    const float* __restrict__ W2, const float* __restrict__ b2,
    const float* __restrict__ W3, const float* __restrict__ b3,
    const int* __restrict__ nidx, const float* __restrict__ ef,
    float* __restrict__ out)
{
    extern __shared__ float sm[];
    float* sW2 = sm;                // 4096
    float* sW3 = sm + 4096;         // 4096
    float* sStg = sm + 8192;        // NWARP * 256
    int tid = threadIdx.x, w = tid>>5, L = tid&31;
    for (int i = tid; i < 4096; i += blockDim.x) {
        sW2[i] = W2[2*4096 + i];
        sW3[i] = W3[2*4096 + i];
    }
    __syncthreads();

    const float* eWc = W1 + 2*131*64 + 128*64;
    float2 wEc[3];
    #pragma unroll
    for (int j = 0; j < 3; j++) wEc[j] = *(const float2*)&eWc[j*64 + 2*L];
    float2 b1c = *(const float2*)&b1[128 + 2*L];
    float2 b2c = *(const float2*)&b2[128 + 2*L];
    float2 b3c = *(const float2*)&b3[128 + 2*L];

    float* st = sStg + w*256;
    for (int t = blockIdx.x*NWARP + w; t < NTASK; t += gridDim.x*NWARP) {
        int p0 = t*PT;
        int bb = p0 >> 13;
        const __half2* Fc = g_F1c + (size_t)bb*NN*32;
        #pragma unroll
        for (int q = 0; q < PT; q++) {
            int p = p0 + q;
            int ii = nidx[p*KK + L];
            float er0 = ef[(size_t)p*96 + L];
            float er1 = ef[(size_t)p*96 + 32 + L];
            float er2 = ef[(size_t)p*96 + 64 + L];
            __half2 mc = __float2half2_rn(-6.0e4f);
            #pragma unroll
            for (int k = 0; k < KK; k++) {
                int fi = __shfl_sync(0xffffffffu, ii, k);
                __half2 v = __ldg(&Fc[(size_t)fi*32 + L]);
                float e0 = EGET(3*k), e1 = EGET(3*k+1), e2 = EGET(3*k+2);
                float ec0 = fmaf(e2, wEc[2].x, fmaf(e1, wEc[1].x, e0*wEc[0].x));
                float ec1 = fmaf(e2, wEc[2].y, fmaf(e1, wEc[1].y, e0*wEc[0].y));
                __half2 ec = __floats2half2_rn(ec0, ec1);
                mc = __hmax2(mc, __hadd2(v, ec));
            }
            float2 fc = __half22float2(mc);
            fc.x = lrelu(fc.x + b1c.x);  fc.y = lrelu(fc.y + b1c.y);
            *(float2*)&st[q*64 + 2*L] = fc;
        }
        __syncwarp();
        float yc[PT][2];
        #pragma unroll
        for (int q = 0; q < PT; q++) { yc[q][0] = b2c.x; yc[q][1] = b2c.y; }
        #pragma unroll 8
        for (int j = 0; j < 64; j++) {
            float2 wv = *(const float2*)&sW2[j*64 + 2*L];
            #pragma unroll
            for (int q = 0; q < PT; q++) {
                float pv = st[q*64 + j];
                yc[q][0] += pv*wv.x; yc[q][1] += pv*wv.y;
            }
        }
        __syncwarp();
        #pragma unroll
        for (int q = 0; q < PT; q++)
            *(float2*)&st[q*64 + 2*L] = make_float2(lrelu(yc[q][0]), lrelu(yc[q][1]));
        __syncwarp();
        float oc[PT][2];
        #pragma unroll
        for (int q = 0; q < PT; q++) { oc[q][0] = b3c.x; oc[q][1] = b3c.y; }
        #pragma unroll 8
        for (int j = 0; j < 64; j++) {
            float2 wv = *(const float2*)&sW3[j*64 + 2*L];
            #pragma unroll
            for (int q = 0; q < PT; q++) {
                float yv = st[q*64 + j];
                oc[q][0] += yv*wv.x; oc[q][1] += yv*wv.y;
            }
        }
        #pragma unroll
        for (int q = 0; q < PT; q++) {
            int p = p0 + q;
            float q0 = tanhf(oc[q][0]), q1 = tanhf(oc[q][1]);
            float2 zv = *(const float2*)&g_z[(size_t)p*64 + 2*L];
            float2 hv = *(const float2*)&h[(size_t)p*64 + 2*L];
            float o0 = hv.x + zv.x*(q0 - hv.x);
            float o1 = hv.y + zv.y*(q1 - hv.y);
            *(float2*)&out[(size_t)p*64 + 2*L] = make_float2(o0, o1);
        }
        __syncwarp();
    }
}

extern "C" void kernel_launch(void* const* d_in, const int* in_sizes, int n_in,
                              void* d_out, int out_size)
{
    const float* h   = (const float*)d_in[0];
    const float* x   = (const float*)d_in[1];
    // d_in[2] = c, unused (matches reference)
    const float* W1  = (const float*)d_in[3];
    const float* b1  = (const float*)d_in[4];
    const float* W2  = (const float*)d_in[5];
    const float* b2  = (const float*)d_in[6];
    const float* W3  = (const float*)d_in[7];
    const float* b3  = (const float*)d_in[8];
    const int*   nidx = (const int*)d_in[9];
    const float* ef  = (const float*)d_in[10];
    float* out = (float*)d_out;

    void *pF1ab, *pF1c, *pz, *prh;
    cudaGetSymbolAddress(&pF1ab, g_F1ab);
    cudaGetSymbolAddress(&pF1c,  g_F1c);
    cudaGetSymbolAddress(&pz,    g_z);
    cudaGetSymbolAddress(&prh,   g_rh);

    const int smem_lin2 = (16384 + NWARP*PT*128) * 4;     // 81920
    const int smem_lin1 = (8192 + NWARP*PT*128) * 4;      // 49152
    const int smem_g01  = (16384 + NWARP*512) * 4;        // 81920
    const int smem_g2   = (8192 + NWARP*256) * 4;         // 40960

    cudaFuncSetAttribute(linear2_kernel, cudaFuncAttributeMaxDynamicSharedMemorySize, smem_lin2);
    cudaFuncSetAttribute(linear1_kernel, cudaFuncAttributeMaxDynamicSharedMemorySize, smem_lin1);
    cudaFuncSetAttribute(gate01_kernel,  cudaFuncAttributeMaxDynamicSharedMemorySize, smem_g01);
    cudaFuncSetAttribute(gate2_kernel,   cudaFuncAttributeMaxDynamicSharedMemorySize, smem_g2);

    const int grid = 592;
    dim3 blk(256);

    // F1ab = [h|x] @ {W1a[0], W1a[1]}  (packed fp16)
    linear2_kernel<<<grid, blk, smem_lin2>>>(h, x, W1, W1 + 131*64, (uint2*)pF1ab);
    // z, r*h
    gate01_kernel<<<grid, blk, smem_g01>>>(h, W1, b1, W2, b2, W3, b3, nidx, ef,
                                           (float*)pz, (float*)prh);
    // F1c = [r*h|x] @ W1a[2]  (fp16)
    linear1_kernel<<<grid, blk, smem_lin1>>>((const float*)prh, x, W1 + 2*131*64, (__half2*)pF1c);
    // q and final output
    gate2_kernel<<<grid, blk, smem_g2>>>(h, W1, b1, W2, b2, W3, b3, nidx, ef, out);
}